// round 6
// baseline (speedup 1.0000x reference)
#include <cuda_runtime.h>
#include <math.h>

#define NMAX 8192
#define TILE 2048
#define TPB  256      // 8 j-lanes x 32 row-pair slots
#define RPC  64       // rows per CTA (32 slots x 2 rows)
#define GMAX 128

__device__ float2 g_part[GMAX];   // per-CTA (sum_logprob, count)
__device__ int    g_done;         // zero-init; reset by last block each run

__device__ __forceinline__ float ex2a(float x) {
    float r; asm("ex2.approx.f32 %0, %1;" : "=f"(r) : "f"(x)); return r;
}

// exp2 on the FMA pipe: magic-number round + deg-5 poly + integer exponent add.
// Valid for |tt| < ~126 (all unmasked pairs); masked pairs are never accumulated.
__device__ __forceinline__ float exp2p(float tt) {
    const float MAGIC = 12582912.0f;   // 1.5 * 2^23
    float r = tt + MAGIC;
    float i = r - MAGIC;               // round-to-nearest(tt), exact
    float f = tt - i;                  // f in [-0.5, 0.5]
    float p = fmaf(f, 0.0013333558f, 0.0096181291f);
    p = fmaf(f, p, 0.0555041086f);
    p = fmaf(f, p, 0.2402265070f);
    p = fmaf(f, p, 0.6931471806f);
    p = fmaf(f, p, 1.0f);
    return __int_as_float(__float_as_int(p) + (__float_as_int(r) << 23));
}

__global__ void __launch_bounds__(TPB) pro_fused(const float* __restrict__ pred,
                                                 const float* __restrict__ ytg,
                                                 float* __restrict__ out,
                                                 int n, int padn, int grid)
{
    __shared__ __align__(16) float su[TILE];   // u_j  = yp_j * (20*log2e)
    __shared__ __align__(16) float sz[TILE];   // z_j  = -u_j * yt_j
    __shared__ __align__(16) float sy[TILE];   // yt_j
    __shared__ float sred[8];
    __shared__ float s_min;
    __shared__ float rlp[RPC], rct[RPC];
    __shared__ int   s_last;
    __shared__ float ft[8], fc[8];

    const float K1  = 28.853900817779268f;     // (1/0.05) * log2(e)
    const float EPS = 1e-8f;

    int t  = threadIdx.x;
    int tx = t & 7;
    int ty = t >> 3;
    int k0 = blockIdx.x * RPC + ty * 2;
    int k1 = k0 + 1;

    float yt0 = (k0 < n) ? ytg[k0] : -1e30f;
    float yt1 = (k1 < n) ? ytg[k1] : -1e30f;
    float yp0 = (k0 < n) ? pred[k0] * 20.0f : 0.0f;
    float yp1 = (k1 < n) ? pred[k1] * 20.0f : 0.0f;
    float e0 = yt0 - EPS;
    float e1 = yt1 - EPS;

    float a0 = 0.0f, a1 = 0.0f;   // row0 accumulators
    float b0 = 0.0f, b1 = 0.0f;   // row1 accumulators
    float mn = 1e30f;

    for (int base = 0; base < padn; base += TILE) {
        __syncthreads();
        for (int i = t; i < TILE; i += TPB) {
            int gi = base + i;
            float y, u;
            if (gi < n) { y = ytg[gi]; u = pred[gi] * K1; mn = fminf(mn, y); }
            else        { y = 1e30f;   u = 0.0f; }
            su[i] = u; sz[i] = -u * y; sy[i] = y;
        }
        __syncthreads();

        const float4* su4 = (const float4*)su;
        const float4* sz4 = (const float4*)sz;
        const float4* sy4 = (const float4*)sy;

        // two float4 groups per loop trip; poly handles 3 of the 16 exps
        #pragma unroll 2
        for (int i = tx; i < TILE / 4; i += 16) {
            // ---- group A: poly for (row0,x) and (row1,x) ----
            {
                float4 u4 = su4[i];
                float4 z4 = sz4[i];
                float4 y4 = sy4[i];
                float v00 = exp2p(fmaf(yt0, u4.x, z4.x));
                float v01 = ex2a (fmaf(yt0, u4.y, z4.y));
                float v02 = ex2a (fmaf(yt0, u4.z, z4.z));
                float v03 = ex2a (fmaf(yt0, u4.w, z4.w));
                if (y4.x < e0) a0 += v00;
                if (y4.y < e0) a1 += v01;
                if (y4.z < e0) a0 += v02;
                if (y4.w < e0) a1 += v03;
                float v10 = exp2p(fmaf(yt1, u4.x, z4.x));
                float v11 = ex2a (fmaf(yt1, u4.y, z4.y));
                float v12 = ex2a (fmaf(yt1, u4.z, z4.z));
                float v13 = ex2a (fmaf(yt1, u4.w, z4.w));
                if (y4.x < e1) b0 += v10;
                if (y4.y < e1) b1 += v11;
                if (y4.z < e1) b0 += v12;
                if (y4.w < e1) b1 += v13;
            }
            // ---- group B: poly for (row0,x) only ----
            {
                float4 u4 = su4[i + 8];
                float4 z4 = sz4[i + 8];
                float4 y4 = sy4[i + 8];
                float v00 = exp2p(fmaf(yt0, u4.x, z4.x));
                float v01 = ex2a (fmaf(yt0, u4.y, z4.y));
                float v02 = ex2a (fmaf(yt0, u4.z, z4.z));
                float v03 = ex2a (fmaf(yt0, u4.w, z4.w));
                if (y4.x < e0) a0 += v00;
                if (y4.y < e0) a1 += v01;
                if (y4.z < e0) a0 += v02;
                if (y4.w < e0) a1 += v03;
                float v10 = ex2a (fmaf(yt1, u4.x, z4.x));
                float v11 = ex2a (fmaf(yt1, u4.y, z4.y));
                float v12 = ex2a (fmaf(yt1, u4.z, z4.z));
                float v13 = ex2a (fmaf(yt1, u4.w, z4.w));
                if (y4.x < e1) b0 += v10;
                if (y4.y < e1) b1 += v11;
                if (y4.z < e1) b0 += v12;
                if (y4.w < e1) b1 += v13;
            }
        }
    }

    // ---- block-wide global min ----
    #pragma unroll
    for (int o = 16; o; o >>= 1) mn = fminf(mn, __shfl_xor_sync(0xffffffffu, mn, o));
    if ((t & 31) == 0) sred[t >> 5] = mn;
    __syncthreads();
    if (t < 8) {
        float v = sred[t];
        #pragma unroll
        for (int o = 4; o; o >>= 1) v = fminf(v, __shfl_xor_sync(0xffu, v, o));
        if (t == 0) s_min = v;
    }
    __syncthreads();
    float ytmin = s_min;

    // ---- reduce the 8 j-lanes per row (all lanes participate) ----
    float s0 = a0 + a1;
    float s1 = b0 + b1;
    #pragma unroll
    for (int o = 1; o < 8; o <<= 1) {
        s0 += __shfl_xor_sync(0xffffffffu, s0, o);
        s1 += __shfl_xor_sync(0xffffffffu, s1, o);
    }

    if (tx == 0) {
        float lp0 = 0.0f, c0 = 0.0f, lp1 = 0.0f, c1 = 0.0f;
        if (k0 < n) {
            float d = yt0 - ytmin;
            if (d > EPS) { float lp = yp0 * d; lp0 = lp - logf(expf(lp) + s0); c0 = 1.0f; }
        }
        if (k1 < n) {
            float d = yt1 - ytmin;
            if (d > EPS) { float lp = yp1 * d; lp1 = lp - logf(expf(lp) + s1); c1 = 1.0f; }
        }
        rlp[ty * 2]     = lp0;  rct[ty * 2]     = c0;
        rlp[ty * 2 + 1] = lp1;  rct[ty * 2 + 1] = c1;
    }
    __syncthreads();

    // ---- publish per-CTA partial, elect last block ----
    if (t == 0) {
        float tot = 0.0f, c = 0.0f;
        #pragma unroll
        for (int i = 0; i < RPC; i++) { tot += rlp[i]; c += rct[i]; }
        g_part[blockIdx.x] = make_float2(tot, c);
        __threadfence();
        int done = atomicAdd(&g_done, 1);
        s_last = (done == grid - 1) ? 1 : 0;
    }
    __syncthreads();

    // ---- last block: deterministic final reduce ----
    if (s_last) {
        __threadfence();
        float tot = 0.0f, cnt = 0.0f;
        if (t < grid) { float2 p = g_part[t]; tot = p.x; cnt = p.y; }
        #pragma unroll
        for (int o = 16; o; o >>= 1) {      // all 256 threads, full warps
            tot += __shfl_xor_sync(0xffffffffu, tot, o);
            cnt += __shfl_xor_sync(0xffffffffu, cnt, o);
        }
        if ((t & 31) == 0) { ft[t >> 5] = tot; fc[t >> 5] = cnt; }
        __syncthreads();
        if (t == 0) {
            float a = 0.0f, b = 0.0f;
            #pragma unroll
            for (int i = 0; i < 8; i++) { a += ft[i]; b += fc[i]; }
            out[0] = (b > 0.0f) ? (-a / b) : 0.0f;
            g_done = 0;   // restore for the next graph replay
        }
    }
}

extern "C" void kernel_launch(void* const* d_in, const int* in_sizes, int n_in,
                              void* d_out, int out_size)
{
    const float* pred = (const float*)d_in[0];   // predict_similarity
    const float* yt   = (const float*)d_in[1];   // true_similarity
    int n = in_sizes[0];
    if (n > NMAX) n = NMAX;
    int padn = ((n + TILE - 1) / TILE) * TILE;
    int grid = (n + RPC - 1) / RPC;              // 128 for n=8192
    if (grid > GMAX) grid = GMAX;

    pro_fused<<<grid, TPB>>>(pred, yt, (float*)d_out, n, padn, grid);
}

// round 7
// speedup vs baseline: 1.2677x; 1.2677x over previous
#include <cuda_runtime.h>
#include <math.h>

#define NMAX 8192
#define TILE 2048
#define TPB  448      // 16 j-lanes x 28 row-pair slots
#define RPC  56       // rows per CTA (28 slots x 2 rows)
#define GMAX 160

__device__ float2 g_part[GMAX];   // per-CTA (sum_logprob, count)
__device__ int    g_done;         // zero-init; reset by last block each run

__device__ __forceinline__ float ex2a(float x) {
    float r; asm("ex2.approx.f32 %0, %1;" : "=f"(r) : "f"(x)); return r;
}

__global__ void __launch_bounds__(TPB) pro_fused(const float* __restrict__ pred,
                                                 const float* __restrict__ ytg,
                                                 float* __restrict__ out,
                                                 int n, int padn, int grid)
{
    __shared__ __align__(16) float su[TILE];   // u_j  = yp_j * (20*log2e)
    __shared__ __align__(16) float sz[TILE];   // z_j  = -u_j * yt_j
    __shared__ __align__(16) float sy[TILE];   // yt_j
    __shared__ float sred[16];
    __shared__ float s_min;
    __shared__ float rlp[RPC], rct[RPC];
    __shared__ int   s_last;
    __shared__ float ft[16], fc[16];

    const float K1  = 28.853900817779268f;     // (1/0.05) * log2(e)
    const float EPS = 1e-8f;

    int t  = threadIdx.x;
    int tx = t & 15;           // 16 j-lanes
    int ty = t >> 4;           // 28 row-pair slots
    int k0 = blockIdx.x * RPC + ty * 2;
    int k1 = k0 + 1;

    float yt0 = (k0 < n) ? ytg[k0] : -1e30f;
    float yt1 = (k1 < n) ? ytg[k1] : -1e30f;
    float yp0 = (k0 < n) ? pred[k0] * 20.0f : 0.0f;
    float yp1 = (k1 < n) ? pred[k1] * 20.0f : 0.0f;
    float e0 = yt0 - EPS;
    float e1 = yt1 - EPS;

    float a0 = 0.0f, a1 = 0.0f;   // row0 accumulators
    float b0 = 0.0f, b1 = 0.0f;   // row1 accumulators
    float mn = 1e30f;

    for (int base = 0; base < padn; base += TILE) {
        __syncthreads();
        for (int i = t; i < TILE; i += TPB) {
            int gi = base + i;
            float y, u;
            if (gi < n) { y = ytg[gi]; u = pred[gi] * K1; mn = fminf(mn, y); }
            else        { y = 1e30f;   u = 0.0f; }
            su[i] = u; sz[i] = -u * y; sy[i] = y;
        }
        __syncthreads();

        const float4* su4 = (const float4*)su;
        const float4* sz4 = (const float4*)sz;
        const float4* sy4 = (const float4*)sy;

        #pragma unroll 4
        for (int i = tx; i < TILE / 4; i += 16) {
            float4 u4 = su4[i];
            float4 z4 = sz4[i];
            float4 y4 = sy4[i];

            // row 0: arg = u*(yt0 - ytj) = fma(yt0, u, z)
            float v00 = ex2a(fmaf(yt0, u4.x, z4.x));
            float v01 = ex2a(fmaf(yt0, u4.y, z4.y));
            float v02 = ex2a(fmaf(yt0, u4.z, z4.z));
            float v03 = ex2a(fmaf(yt0, u4.w, z4.w));
            if (y4.x < e0) a0 += v00;
            if (y4.y < e0) a1 += v01;
            if (y4.z < e0) a0 += v02;
            if (y4.w < e0) a1 += v03;

            // row 1 reuses the same smem values
            float v10 = ex2a(fmaf(yt1, u4.x, z4.x));
            float v11 = ex2a(fmaf(yt1, u4.y, z4.y));
            float v12 = ex2a(fmaf(yt1, u4.z, z4.z));
            float v13 = ex2a(fmaf(yt1, u4.w, z4.w));
            if (y4.x < e1) b0 += v10;
            if (y4.y < e1) b1 += v11;
            if (y4.z < e1) b0 += v12;
            if (y4.w < e1) b1 += v13;
        }
    }

    // ---- block-wide global min ----
    #pragma unroll
    for (int o = 16; o; o >>= 1) mn = fminf(mn, __shfl_xor_sync(0xffffffffu, mn, o));
    if ((t & 31) == 0) sred[t >> 5] = mn;
    __syncthreads();
    if (t < 32) {                                  // full warp: safe full-mask shfl
        float v = (t < (TPB / 32)) ? sred[t] : 1e30f;
        #pragma unroll
        for (int o = 16; o; o >>= 1) v = fminf(v, __shfl_xor_sync(0xffffffffu, v, o));
        if (t == 0) s_min = v;
    }
    __syncthreads();
    float ytmin = s_min;

    // ---- reduce the 16 j-lanes per row (all lanes participate) ----
    float s0 = a0 + a1;
    float s1 = b0 + b1;
    #pragma unroll
    for (int o = 1; o < 16; o <<= 1) {
        s0 += __shfl_xor_sync(0xffffffffu, s0, o);
        s1 += __shfl_xor_sync(0xffffffffu, s1, o);
    }

    if (tx == 0) {
        float lp0 = 0.0f, c0 = 0.0f, lp1 = 0.0f, c1 = 0.0f;
        if (k0 < n) {
            float d = yt0 - ytmin;
            if (d > EPS) { float lp = yp0 * d; lp0 = lp - logf(expf(lp) + s0); c0 = 1.0f; }
        }
        if (k1 < n) {
            float d = yt1 - ytmin;
            if (d > EPS) { float lp = yp1 * d; lp1 = lp - logf(expf(lp) + s1); c1 = 1.0f; }
        }
        rlp[ty * 2]     = lp0;  rct[ty * 2]     = c0;
        rlp[ty * 2 + 1] = lp1;  rct[ty * 2 + 1] = c1;
    }
    __syncthreads();

    // ---- publish per-CTA partial, elect last block ----
    if (t == 0) {
        float tot = 0.0f, c = 0.0f;
        #pragma unroll
        for (int i = 0; i < RPC; i++) { tot += rlp[i]; c += rct[i]; }
        g_part[blockIdx.x] = make_float2(tot, c);
        __threadfence();
        int done = atomicAdd(&g_done, 1);
        s_last = (done == grid - 1) ? 1 : 0;
    }
    __syncthreads();

    // ---- last block: deterministic final reduce ----
    if (s_last) {
        __threadfence();
        float tot = 0.0f, cnt = 0.0f;
        if (t < grid) { float2 p = g_part[t]; tot = p.x; cnt = p.y; }
        #pragma unroll
        for (int o = 16; o; o >>= 1) {             // all threads, full warps
            tot += __shfl_xor_sync(0xffffffffu, tot, o);
            cnt += __shfl_xor_sync(0xffffffffu, cnt, o);
        }
        if ((t & 31) == 0) { ft[t >> 5] = tot; fc[t >> 5] = cnt; }
        __syncthreads();
        if (t == 0) {
            float a = 0.0f, b = 0.0f;
            #pragma unroll
            for (int i = 0; i < TPB / 32; i++) { a += ft[i]; b += fc[i]; }
            out[0] = (b > 0.0f) ? (-a / b) : 0.0f;
            g_done = 0;   // restore for the next graph replay
        }
    }
}

extern "C" void kernel_launch(void* const* d_in, const int* in_sizes, int n_in,
                              void* d_out, int out_size)
{
    const float* pred = (const float*)d_in[0];   // predict_similarity
    const float* yt   = (const float*)d_in[1];   // true_similarity
    int n = in_sizes[0];
    if (n > NMAX) n = NMAX;
    int padn = ((n + TILE - 1) / TILE) * TILE;
    int grid = (n + RPC - 1) / RPC;              // 147 for n=8192
    if (grid > GMAX) grid = GMAX;

    pro_fused<<<grid, TPB>>>(pred, yt, (float*)d_out, n, padn, grid);
}